// round 2
// baseline (speedup 1.0000x reference)
#include <cuda_runtime.h>

// Fused: y[t][j] = x[t][j] * W[j][j], one float4 per thread.
// TOKENS=8192, IN_FEATURES=4096 -> 8,388,608 float4 elements.
// Diag values are read directly from the dense W at stride 4097:
// only 4096 distinct cache lines (512KB), L2-resident after first wave.
__global__ void fused_diag_scale_kernel(const float4* __restrict__ x,
                                        const float* __restrict__ W,
                                        float4* __restrict__ y) {
    unsigned int i = blockIdx.x * blockDim.x + threadIdx.x;  // float4 index
    unsigned int c = (i & 1023u) << 2;                       // first diag col

    // Streaming load of x (no reuse — evict-first keeps L2 for the diag).
    float4 v = __ldcs(&x[i]);

    // Diagonal: W[j*4096 + j] = W[j*4097]. Default (caching) loads — these
    // lines are hot in L2 across all 8192 token rows.
    float d0 = __ldg(&W[(size_t)(c + 0) * 4097u]);
    float d1 = __ldg(&W[(size_t)(c + 1) * 4097u]);
    float d2 = __ldg(&W[(size_t)(c + 2) * 4097u]);
    float d3 = __ldg(&W[(size_t)(c + 3) * 4097u]);

    v.x *= d0;
    v.y *= d1;
    v.z *= d2;
    v.w *= d3;

    // Streaming store of y (write-once).
    __stcs(&y[i], v);
}

extern "C" void kernel_launch(void* const* d_in, const int* in_sizes, int n_in,
                              void* d_out, int out_size) {
    const float* x = (const float*)d_in[0];
    const float* W = (const float*)d_in[1];
    float* y = (float*)d_out;

    // 8,388,608 float4 -> 32768 blocks x 256 threads, single graph node.
    fused_diag_scale_kernel<<<32768, 256>>>((const float4*)x, W, (float4*)y);
}

// round 3
// speedup vs baseline: 2.0767x; 2.0767x over previous
#include <cuda_runtime.h>

// y[t][j] = x[t][j] * W[j][j], fused, diag amortized over ROWS_PER_THREAD rows.
//
// Geometry: 8192 tokens x 4096 features = 8192 x 1024 float4.
// Each thread owns one float4 column (c4 in [0,1024)) and 32 consecutive rows.
// Diag loaded ONCE per thread (4 strided scalar LDGs), then 32 coalesced
// load/scale/store iterations. Strided-load wavefront cost cut 32x vs R2.
#define ROWS_PER_THREAD 32
#define ROW_F4 1024u   // float4 per row

__global__ void fused_diag_scale_rows_kernel(const float4* __restrict__ x,
                                             const float* __restrict__ W,
                                             float4* __restrict__ y) {
    const unsigned int c4 = blockIdx.x * blockDim.x + threadIdx.x;  // 0..1023
    const unsigned int row0 = blockIdx.y * ROWS_PER_THREAD;
    const unsigned int c = c4 << 2;  // first scalar column

    // Diagonal once per thread: W[j*4096 + j] = W[j*4097].
    float4 d;
    d.x = __ldg(&W[(size_t)(c + 0) * 4097u]);
    d.y = __ldg(&W[(size_t)(c + 1) * 4097u]);
    d.z = __ldg(&W[(size_t)(c + 2) * 4097u]);
    d.w = __ldg(&W[(size_t)(c + 3) * 4097u]);

    const float4* xp = x + (size_t)row0 * ROW_F4 + c4;
    float4*       yp = y + (size_t)row0 * ROW_F4 + c4;

    #pragma unroll 8
    for (int r = 0; r < ROWS_PER_THREAD; r++) {
        float4 v = __ldcs(xp + (size_t)r * ROW_F4);  // stream x (no reuse)
        v.x *= d.x;
        v.y *= d.y;
        v.z *= d.z;
        v.w *= d.w;
        __stcs(yp + (size_t)r * ROW_F4, v);          // stream y (write-once)
    }
}

extern "C" void kernel_launch(void* const* d_in, const int* in_sizes, int n_in,
                              void* d_out, int out_size) {
    const float* x = (const float*)d_in[0];
    const float* W = (const float*)d_in[1];
    float* y = (float*)d_out;

    // grid.x: 4 blocks x 256 threads = 1024 float4 columns
    // grid.y: 8192 rows / 32 rows-per-thread = 256
    dim3 grid(4, 256);
    fused_diag_scale_rows_kernel<<<grid, 256>>>((const float4*)x, W, (float4*)y);
}

// round 4
// speedup vs baseline: 2.1564x; 1.0384x over previous
#include <cuda_runtime.h>

// Scratch for the extracted diagonal (allocation-free: __device__ global).
__device__ float g_diag[4096];

// Kernel A: pull diag(W) out of the dense [4096,4096] matrix (~0.7us).
__global__ void extract_diag_kernel(const float* __restrict__ W) {
    int j = blockIdx.x * blockDim.x + threadIdx.x;
    if (j < 4096) {
        g_diag[j] = __ldg(&W[(size_t)j * 4097u]);
    }
}

// Kernel B: y = x * diag (columnwise), pure linear stream.
// 8,388,608 float4 total. ILP=2: thread i handles float4 i and i+HALF.
// HALF = 4,194,304 is a multiple of 1024 (float4 per row), so both elements
// share the same column -> one diag load serves both.
#define HALF 4194304u

__global__ void diag_scale_kernel(const float4* __restrict__ x,
                                  float4* __restrict__ y) {
    const unsigned int i = blockIdx.x * blockDim.x + threadIdx.x;  // < HALF
    const float4* d4 = reinterpret_cast<const float4*>(g_diag);

    const float4 d = __ldg(&d4[i & 1023u]);   // L1/L2-hot 16KB table

    float4 a = __ldcs(&x[i]);                 // stream, evict-first
    float4 b = __ldcs(&x[i + HALF]);

    a.x *= d.x; a.y *= d.y; a.z *= d.z; a.w *= d.w;
    b.x *= d.x; b.y *= d.y; b.z *= d.z; b.w *= d.w;

    __stcs(&y[i], a);                         // write-once, evict-first
    __stcs(&y[i + HALF], b);
}

extern "C" void kernel_launch(void* const* d_in, const int* in_sizes, int n_in,
                              void* d_out, int out_size) {
    const float* x = (const float*)d_in[0];
    const float* W = (const float*)d_in[1];
    float* y = (float*)d_out;

    extract_diag_kernel<<<16, 256>>>(W);

    // HALF threads, each doing 2 float4: 4,194,304 / 256 = 16384 blocks.
    diag_scale_kernel<<<16384, 256>>>((const float4*)x, (float4*)y);
}